// round 1
// baseline (speedup 1.0000x reference)
#include <cuda_runtime.h>
#include <cuda_bf16.h>
#include <math.h>

// Problem constants
#define B_  4
#define C_  64
#define HA_ 512
#define WA_ 512
#define N_  256
#define HB_ 32
#define WB_ 32
#define PLANE_ (HA_ * WA_)          // 262144
#define POS_   (HB_ * WB_)          // 1024 positions per patch
#define THREADS_ 256
#define POS_PER_THREAD_ 4

__global__ __launch_bounds__(THREADS_)
void aerial_patch_sampler_kernel(const float* __restrict__ feat,
                                 const float* __restrict__ pose,
                                 float* __restrict__ out) {
    const int n = blockIdx.x;        // patch index
    const int b = blockIdx.y;        // batch index
    const int tid = threadIdx.x;

    // Pose for this (b, n): broadcast loads
    const float* pp = pose + ((size_t)b * N_ + n) * 3;
    const float u_off = pp[0];
    const float v_off = pp[1];
    const float theta = pp[2];
    float s, c;
    sincosf(theta, &s, &c);
    const float cos_r = c;       // cos(-theta) = cos(theta)
    const float sin_r = -s;      // sin(-theta) = -sin(theta)

    // Per-position constants (4 positions per thread, consecutive for STG.128)
    int   idx00[POS_PER_THREAD_], idx10[POS_PER_THREAD_];
    int   idx01[POS_PER_THREAD_], idx11[POS_PER_THREAD_];
    float w00[POS_PER_THREAD_], w10[POS_PER_THREAD_];
    float w01[POS_PER_THREAD_], w11[POS_PER_THREAD_];

    #pragma unroll
    for (int k = 0; k < POS_PER_THREAD_; ++k) {
        const int pos = tid * POS_PER_THREAD_ + k;
        const int hb = pos >> 5;         // / WB_
        const int wb = pos & 31;         // % WB_

        const float gu0 = (float)(HB_ - 1 - hb);
        const float gv0 = (float)(wb - WB_ / 2);

        const float gu = u_off + cos_r * gu0 - sin_r * gv0;
        const float gv = v_off + sin_r * gu0 + cos_r * gv0;

        // normalized coords (FEATURE_SCALE = 1)
        float gx = (gu + 0.5f) * (2.0f / (float)WA_) - 1.0f;
        float gy = (gv + 0.5f) * (2.0f / (float)HA_) - 1.0f;
        const bool valid = (fabsf(gx) < 1.0f) && (fabsf(gy) < 1.0f);
        if (!valid) { gx = 2.0f; gy = 2.0f; }

        // unnormalize (align_corners=False)
        const float ix = ((gx + 1.0f) * (float)WA_ - 1.0f) * 0.5f;
        const float iy = ((gy + 1.0f) * (float)HA_ - 1.0f) * 0.5f;

        const float x0f = floorf(ix);
        const float y0f = floorf(iy);
        const float wx1 = ix - x0f;
        const float wx0 = 1.0f - wx1;
        const float wy1 = iy - y0f;
        const float wy0 = 1.0f - wy1;

        const int x0 = (int)x0f;
        const int y0 = (int)y0f;
        const int x1 = x0 + 1;
        const int y1 = y0 + 1;

        const bool vx0 = (x0 >= 0) && (x0 < WA_);
        const bool vx1 = (x1 >= 0) && (x1 < WA_);
        const bool vy0 = (y0 >= 0) && (y0 < HA_);
        const bool vy1 = (y1 >= 0) && (y1 < HA_);

        const int x0c = min(max(x0, 0), WA_ - 1);
        const int x1c = min(max(x1, 0), WA_ - 1);
        const int y0c = min(max(y0, 0), HA_ - 1);
        const int y1c = min(max(y1, 0), HA_ - 1);

        idx00[k] = y0c * WA_ + x0c;
        idx10[k] = y0c * WA_ + x1c;
        idx01[k] = y1c * WA_ + x0c;
        idx11[k] = y1c * WA_ + x1c;

        w00[k] = (vx0 && vy0) ? (wx0 * wy0) : 0.0f;
        w10[k] = (vx1 && vy0) ? (wx1 * wy0) : 0.0f;
        w01[k] = (vx0 && vy1) ? (wx0 * wy1) : 0.0f;
        w11[k] = (vx1 && vy1) ? (wx1 * wy1) : 0.0f;
    }

    const float* plane = feat + (size_t)b * C_ * PLANE_;
    float* outp = out + (((size_t)b * N_ + n) * C_) * (size_t)POS_
                      + (size_t)tid * POS_PER_THREAD_;

    #pragma unroll 2
    for (int ch = 0; ch < C_; ++ch) {
        const float* base = plane + (size_t)ch * PLANE_;
        float4 res;
        float acc[POS_PER_THREAD_];
        #pragma unroll
        for (int k = 0; k < POS_PER_THREAD_; ++k) {
            const float v00 = __ldg(base + idx00[k]);
            const float v10 = __ldg(base + idx10[k]);
            const float v01 = __ldg(base + idx01[k]);
            const float v11 = __ldg(base + idx11[k]);
            acc[k] = v00 * w00[k] + v10 * w10[k] + v01 * w01[k] + v11 * w11[k];
        }
        res.x = acc[0]; res.y = acc[1]; res.z = acc[2]; res.w = acc[3];
        *reinterpret_cast<float4*>(outp + (size_t)ch * POS_) = res;
    }
}

extern "C" void kernel_launch(void* const* d_in, const int* in_sizes, int n_in,
                              void* d_out, int out_size) {
    const float* aer_feat = (const float*)d_in[0];
    const float* pose_uvr = (const float*)d_in[1];
    float* out = (float*)d_out;

    dim3 grid(N_, B_);
    dim3 block(THREADS_);
    aerial_patch_sampler_kernel<<<grid, block>>>(aer_feat, pose_uvr, out);
}